// round 4
// baseline (speedup 1.0000x reference)
#include <cuda_runtime.h>

// QuantizedAdd: per-sample (cluster-gathered) gemmlowp requantize of two int32
// tensors, add, +z3, clamp to [-128,127]. Harness output buffer is float32
// (int64 reference values fit exactly), so we store float4.
//
// Input ORDER resolved at runtime from in_sizes (dict vs alphabetical).

#define THREADS 256

// Bit-exact replica of the reference requantize path; 64-bit math confined to
// one IMAD.WIDE (nudge folded into the wide-multiply addend).
// d = (x - z) << lsh ; v = (d*M0 + nudge) >> 31 (floor, matches jnp >>).
// |d| <= 1020, M0 < 2^31 -> |v| <= 1020 fits int32. RoundingDivideByPOT in 32b.
__device__ __forceinline__ int rq(int x, int z, int lsh, int M0,
                                  unsigned mask, int thr_base, int rsh)
{
    int d = (x - z) << lsh;
    long long nudge = (d >= 0) ? (1LL << 30) : (1LL - (1LL << 30));
    long long prod = (long long)d * (long long)M0 + nudge;   // IMAD.WIDE
    int v = (int)(prod >> 31);                               // funnel shift
    unsigned rem = (unsigned)v & mask;
    unsigned thr = (unsigned)(thr_base + (v < 0 ? 1 : 0));
    return (v >> rsh) + (rem > thr ? 1 : 0);
}

__global__ void __launch_bounds__(THREADS)
qadd_kernel(const int4* __restrict__ bypass,
            const int4* __restrict__ prev,
            const int* __restrict__ batch_cluster,
            const int* __restrict__ z_bypass,
            const int* __restrict__ z_prev,
            const int* __restrict__ z3_arr,
            const int* __restrict__ M0_bypass,
            const int* __restrict__ M0_prev,
            const int* __restrict__ shift_bypass,
            const int* __restrict__ shift_prev,
            float4* __restrict__ out,
            int nv4)   // (C*H*W)/4 per sample
{
    const int b = blockIdx.y;

    const int c  = __ldg(&batch_cluster[b]);
    const int z1 = __ldg(&z_bypass[c]);
    const int z2 = __ldg(&z_prev[c]);
    const int z3 = __ldg(&z3_arr[c]);
    const int M1 = __ldg(&M0_bypass[c]);
    const int M2 = __ldg(&M0_prev[c]);
    const int s1 = __ldg(&shift_bypass[c]);
    const int s2 = __ldg(&shift_prev[c]);

    const int lsh1 = s1 < 0 ? -s1 : 0;
    const int rsh1 = s1 < 0 ? 0 : s1;
    const int lsh2 = s2 < 0 ? -s2 : 0;
    const int rsh2 = s2 < 0 ? 0 : s2;
    const unsigned mask1 = (1u << rsh1) - 1u;
    const unsigned mask2 = (1u << rsh2) - 1u;
    const int thrb1 = (int)(mask1 >> 1);
    const int thrb2 = (int)(mask2 >> 1);

    const size_t sbase = (size_t)b * (size_t)nv4;
    const int stride = gridDim.x * THREADS;

    for (int i = blockIdx.x * THREADS + threadIdx.x; i < nv4; i += stride) {
        const int4 xb = bypass[sbase + i];
        const int4 xp = prev[sbase + i];

        int r0 = rq(xb.x, z1, lsh1, M1, mask1, thrb1, rsh1)
               + rq(xp.x, z2, lsh2, M2, mask2, thrb2, rsh2) + z3;
        int r1 = rq(xb.y, z1, lsh1, M1, mask1, thrb1, rsh1)
               + rq(xp.y, z2, lsh2, M2, mask2, thrb2, rsh2) + z3;
        int r2 = rq(xb.z, z1, lsh1, M1, mask1, thrb1, rsh1)
               + rq(xp.z, z2, lsh2, M2, mask2, thrb2, rsh2) + z3;
        int r3 = rq(xb.w, z1, lsh1, M1, mask1, thrb1, rsh1)
               + rq(xp.w, z2, lsh2, M2, mask2, thrb2, rsh2) + z3;

        float4 o;
        o.x = (float)max(-128, min(127, r0));
        o.y = (float)max(-128, min(127, r1));
        o.z = (float)max(-128, min(127, r2));
        o.w = (float)max(-128, min(127, r3));
        out[sbase + i] = o;
    }
}

extern "C" void kernel_launch(void* const* d_in, const int* in_sizes, int n_in,
                              void* d_out, int out_size)
{
    // ---- resolve input mapping from sizes (host-only, no device access) ----
    int bigIdx[2] = {0, 1};  int nbig = 0;
    int smallIdx[8] = {0,0,0,0,0,0,0,0}; int nsmall = 0;
    int bcIdx = 2;

    for (int i = 0; i < n_in; i++) {
        if (in_sizes[i] > 100000) {            // tensor inputs
            if (nbig < 2) bigIdx[nbig] = i;
            nbig++;
        } else if (in_sizes[i] <= 64) {        // 8-entry cluster params
            if (nsmall < 8) smallIdx[nsmall++] = i;
        } else {
            bcIdx = i;                          // size-B batch_cluster
        }
    }

    const int4* bypass = (const int4*)d_in[bigIdx[0]];
    const int4* prev   = (const int4*)d_in[bigIdx[1]];
    const int*  bc     = (const int*)d_in[bcIdx];

    const int *z1, *z2, *z3, *M1, *M2, *s1, *s2;
    if (in_sizes[0] > 100000) {
        // dict order: z_bypass, z_prev, z3, M0_bypass, M0_prev, shift_bypass, shift_prev
        z1 = (const int*)d_in[smallIdx[0]];
        z2 = (const int*)d_in[smallIdx[1]];
        z3 = (const int*)d_in[smallIdx[2]];
        M1 = (const int*)d_in[smallIdx[3]];
        M2 = (const int*)d_in[smallIdx[4]];
        s1 = (const int*)d_in[smallIdx[5]];
        s2 = (const int*)d_in[smallIdx[6]];
    } else {
        // alphabetical: M0_bypass, M0_prev, shift_bypass, shift_prev, z3, z_bypass, z_prev
        M1 = (const int*)d_in[smallIdx[0]];
        M2 = (const int*)d_in[smallIdx[1]];
        s1 = (const int*)d_in[smallIdx[2]];
        s2 = (const int*)d_in[smallIdx[3]];
        z3 = (const int*)d_in[smallIdx[4]];
        z1 = (const int*)d_in[smallIdx[5]];
        z2 = (const int*)d_in[smallIdx[6]];
    }

    const int B   = in_sizes[bcIdx];               // 128
    const int chw = in_sizes[bigIdx[0]] / B;       // 200704, divisible by 4
    const int nv4 = chw / 4;                       // 50176

    int gx = (nv4 + THREADS * 4 - 1) / (THREADS * 4);   // 49 -> 4 iters/thread
    dim3 grid(gx, B);

    qadd_kernel<<<grid, THREADS>>>(bypass, prev, bc, z1, z2, z3, M1, M2, s1, s2,
                                   (float4*)d_out, nv4);
}

// round 5
// speedup vs baseline: 1.0050x; 1.0050x over previous
#include <cuda_runtime.h>

// QuantizedAdd via per-block shared-memory LUTs.
// Requantized output depends only on the 8-bit input value and the per-cluster
// params, so each block builds lut1[256] (= rq_bypass + z3) and lut2[256]
// (= rq_prev); the streaming loop is then 2 LDS + add + clamp + cvt per elem.
// Output buffer is float32 (established R4). Bit-exact integer path retained
// in the LUT builder.

#define THREADS 256

__device__ __forceinline__ int rq(int x, int z, int lsh, int M0,
                                  unsigned mask, int thr_base, int rsh)
{
    int d = (x - z) << lsh;
    long long nudge = (d >= 0) ? (1LL << 30) : (1LL - (1LL << 30));
    long long prod = (long long)d * (long long)M0 + nudge;   // IMAD.WIDE
    int v = (int)(prod >> 31);                               // |v| <= 1020
    unsigned rem = (unsigned)v & mask;
    unsigned thr = (unsigned)(thr_base + (v < 0 ? 1 : 0));
    return (v >> rsh) + (rem > thr ? 1 : 0);
}

__global__ void __launch_bounds__(THREADS)
qadd_kernel(const int4* __restrict__ bypass,
            const int4* __restrict__ prev,
            const int* __restrict__ batch_cluster,
            const int* __restrict__ z_bypass,
            const int* __restrict__ z_prev,
            const int* __restrict__ z3_arr,
            const int* __restrict__ M0_bypass,
            const int* __restrict__ M0_prev,
            const int* __restrict__ shift_bypass,
            const int* __restrict__ shift_prev,
            float4* __restrict__ out,
            int nv4)   // (C*H*W)/4 per sample
{
    __shared__ int lut1[256];
    __shared__ int lut2[256];

    const int b = blockIdx.y;
    const int t = threadIdx.x;

    // ---- build LUTs (each thread: one entry per table) ----
    {
        const int c  = __ldg(&batch_cluster[b]);
        const int z1 = __ldg(&z_bypass[c]);
        const int z2 = __ldg(&z_prev[c]);
        const int z3 = __ldg(&z3_arr[c]);
        const int M1 = __ldg(&M0_bypass[c]);
        const int M2 = __ldg(&M0_prev[c]);
        const int s1 = __ldg(&shift_bypass[c]);
        const int s2 = __ldg(&shift_prev[c]);

        const int lsh1 = s1 < 0 ? -s1 : 0;
        const int rsh1 = s1 < 0 ? 0 : s1;
        const int lsh2 = s2 < 0 ? -s2 : 0;
        const int rsh2 = s2 < 0 ? 0 : s2;
        const unsigned mask1 = (1u << rsh1) - 1u;
        const unsigned mask2 = (1u << rsh2) - 1u;

        lut1[t] = rq(t, z1, lsh1, M1, mask1, (int)(mask1 >> 1), rsh1) + z3;
        lut2[t] = rq(t, z2, lsh2, M2, mask2, (int)(mask2 >> 1), rsh2);
    }
    __syncthreads();

    const size_t sbase = (size_t)b * (size_t)nv4;
    const int stride = gridDim.x * THREADS;

    for (int i = blockIdx.x * THREADS + t; i < nv4; i += stride) {
        const int4 xb = bypass[sbase + i];
        const int4 xp = prev[sbase + i];

        int r0 = lut1[xb.x] + lut2[xp.x];
        int r1 = lut1[xb.y] + lut2[xp.y];
        int r2 = lut1[xb.z] + lut2[xp.z];
        int r3 = lut1[xb.w] + lut2[xp.w];

        float4 o;
        o.x = (float)max(-128, min(127, r0));
        o.y = (float)max(-128, min(127, r1));
        o.z = (float)max(-128, min(127, r2));
        o.w = (float)max(-128, min(127, r3));
        out[sbase + i] = o;
    }
}

extern "C" void kernel_launch(void* const* d_in, const int* in_sizes, int n_in,
                              void* d_out, int out_size)
{
    // ---- resolve input mapping from sizes (host-only) ----
    int bigIdx[2] = {0, 1};  int nbig = 0;
    int smallIdx[8] = {0,0,0,0,0,0,0,0}; int nsmall = 0;
    int bcIdx = 2;

    for (int i = 0; i < n_in; i++) {
        if (in_sizes[i] > 100000) {
            if (nbig < 2) bigIdx[nbig] = i;
            nbig++;
        } else if (in_sizes[i] <= 64) {
            if (nsmall < 8) smallIdx[nsmall++] = i;
        } else {
            bcIdx = i;
        }
    }

    const int4* bypass = (const int4*)d_in[bigIdx[0]];
    const int4* prev   = (const int4*)d_in[bigIdx[1]];
    const int*  bc     = (const int*)d_in[bcIdx];

    const int *z1, *z2, *z3, *M1, *M2, *s1, *s2;
    if (in_sizes[0] > 100000) {
        // dict order: z_bypass, z_prev, z3, M0_bypass, M0_prev, shift_bypass, shift_prev
        z1 = (const int*)d_in[smallIdx[0]];
        z2 = (const int*)d_in[smallIdx[1]];
        z3 = (const int*)d_in[smallIdx[2]];
        M1 = (const int*)d_in[smallIdx[3]];
        M2 = (const int*)d_in[smallIdx[4]];
        s1 = (const int*)d_in[smallIdx[5]];
        s2 = (const int*)d_in[smallIdx[6]];
    } else {
        // alphabetical: M0_bypass, M0_prev, shift_bypass, shift_prev, z3, z_bypass, z_prev
        M1 = (const int*)d_in[smallIdx[0]];
        M2 = (const int*)d_in[smallIdx[1]];
        s1 = (const int*)d_in[smallIdx[2]];
        s2 = (const int*)d_in[smallIdx[3]];
        z3 = (const int*)d_in[smallIdx[4]];
        z1 = (const int*)d_in[smallIdx[5]];
        z2 = (const int*)d_in[smallIdx[6]];
    }

    const int B   = in_sizes[bcIdx];               // 128
    const int chw = in_sizes[bigIdx[0]] / B;       // 200704
    const int nv4 = chw / 4;                       // 50176

    int gx = (nv4 + THREADS * 4 - 1) / (THREADS * 4);   // 49 -> 4 iters/thread
    dim3 grid(gx, B);

    qadd_kernel<<<grid, THREADS>>>(bypass, prev, bc, z1, z2, z3, M1, M2, s1, s2,
                                   (float4*)d_out, nv4);
}